// round 13
// baseline (speedup 1.0000x reference)
#include <cuda_runtime.h>
#include <cuda_fp16.h>
#include <cstdint>
#include <math.h>

#define D_MODEL 1024
#define D_FF    2048
#define NE      8
#define CAP     4096
#define MAXT    4096

// ---- device scratch (planes written ONLY from device code) ----
__device__ __align__(16) __half g_xhi[MAXT * D_MODEL];
__device__ __align__(16) __half g_xlo[MAXT * D_MODEL];
__device__ __align__(16) __half g_Hhi[2 * MAXT * D_FF];
__device__ __align__(16) __half g_Hlo[2 * MAXT * D_FF];
__device__ __align__(16) __half g_W1hi[NE * D_FF * D_MODEL];   // [e][n][k]
__device__ __align__(16) __half g_W1lo[NE * D_FF * D_MODEL];
__device__ __align__(16) __half g_W2hi[NE * D_MODEL * D_FF];   // [e][n][k]
__device__ __align__(16) __half g_W2lo[NE * D_MODEL * D_FF];
__device__ int   g_tok[NE * CAP];
__device__ float g_wt[NE * CAP];
__device__ int   g_cnt[NE];
__device__ int   g_off[NE];
__device__ float g_imp[NE];

// ======================= portable PTX helpers ==============================
__device__ __forceinline__ uint32_t smem_u32(const void* p) {
    uint32_t a;
    asm("{ .reg .u64 t; cvta.to.shared.u64 t, %1; cvt.u32.u64 %0, t; }" : "=r"(a) : "l"(p));
    return a;
}
__device__ __forceinline__ void cp16(uint32_t smem, const void* g) {
    asm volatile("cp.async.cg.shared.global [%0], [%1], 16;" :: "r"(smem), "l"(g));
}
#define CP_COMMIT() asm volatile("cp.async.commit_group;" ::: "memory")
#define CP_WAIT(n)  asm volatile("cp.async.wait_group %0;" :: "n"(n) : "memory")

__device__ __forceinline__ void mma_f16(float* c,
                                        uint32_t a0, uint32_t a1, uint32_t a2, uint32_t a3,
                                        uint32_t b0, uint32_t b1) {
    asm volatile(
        "mma.sync.aligned.m16n8k16.row.col.f32.f16.f16.f32 "
        "{%0,%1,%2,%3}, {%4,%5,%6,%7}, {%8,%9}, {%0,%1,%2,%3};"
        : "+f"(c[0]), "+f"(c[1]), "+f"(c[2]), "+f"(c[3])
        : "r"(a0), "r"(a1), "r"(a2), "r"(a3), "r"(b0), "r"(b1));
}
__device__ __forceinline__ void ldmx4(uint32_t& r0, uint32_t& r1, uint32_t& r2, uint32_t& r3,
                                      uint32_t addr) {
    asm volatile("ldmatrix.sync.aligned.m8n8.x4.shared.b16 {%0,%1,%2,%3}, [%4];"
                 : "=r"(r0), "=r"(r1), "=r"(r2), "=r"(r3) : "r"(addr));
}
__device__ __forceinline__ void hsplit(float v, __half& h, __half& l) {
    h = __float2half(v);
    l = __float2half(v - __half2float(h));
}

// ======================= prep kernels ======================================
__global__ void split_x_kernel(const float* __restrict__ x, int n) {
    int i = blockIdx.x * blockDim.x + threadIdx.x;
    if (i < n) {
        __half h, l;
        hsplit(x[i], h, l);
        g_xhi[i] = h; g_xlo[i] = l;
    }
}

// W[e][K][N] fp32 -> hi/lo [e][N][K] fp16; symbols referenced in-device only
// (host-side symbol decay of __device__ arrays = R5/R6/R8 silent-garbage bug).
template<int K, int N>
__device__ __forceinline__ void split_w_body(const float* __restrict__ W,
                                             __half* __restrict__ Whi,
                                             __half* __restrict__ Wlo) {
    __shared__ float tile[32][33];
    const int e = blockIdx.z;
    const int k0 = blockIdx.y * 32, n0 = blockIdx.x * 32;
    const int tx = threadIdx.x, ty = threadIdx.y;   // 32 x 8
    const float* Wb = W + (size_t)e * K * N;
#pragma unroll
    for (int r = 0; r < 4; r++)
        tile[ty + r * 8][tx] = Wb[(size_t)(k0 + ty + r * 8) * N + n0 + tx];
    __syncthreads();
    __half* oh = Whi + (size_t)e * K * N;
    __half* ol = Wlo + (size_t)e * K * N;
#pragma unroll
    for (int r = 0; r < 4; r++) {
        int n = n0 + ty + r * 8;
        float v = tile[tx][ty + r * 8];
        __half h, l;
        hsplit(v, h, l);
        oh[(size_t)n * K + k0 + tx] = h;
        ol[(size_t)n * K + k0 + tx] = l;
    }
}
__global__ void split_w1_kernel(const float* __restrict__ W) {
    split_w_body<D_MODEL, D_FF>(W, g_W1hi, g_W1lo);
}
__global__ void split_w2_kernel(const float* __restrict__ W) {
    split_w_body<D_FF, D_MODEL>(W, g_W2hi, g_W2lo);
}

// ======================= small kernels =====================================
__global__ void zero_kernel(float* out, int n) {
    int i = blockIdx.x * blockDim.x + threadIdx.x;
    if (i < n) out[i] = 0.0f;
    if (blockIdx.x == 0 && threadIdx.x < NE) { g_cnt[threadIdx.x] = 0; g_imp[threadIdx.x] = 0.0f; }
}

// block-per-token router, ONE float4 x-load per thread (4x MLP vs R12)
__global__ void router_kernel(const float* __restrict__ x,
                              const float* __restrict__ rw,
                              const float* __restrict__ rb) {
    const int t = blockIdx.x, tid = threadIdx.x;
    float part[NE];
#pragma unroll
    for (int e = 0; e < NE; e++) part[e] = 0.0f;
    float4 xv4 = ((const float4*)(x + (size_t)t * D_MODEL))[tid];
    const int d0 = tid * 4;
#pragma unroll
    for (int j = 0; j < 4; j++) {
        float xv = (j == 0) ? xv4.x : (j == 1) ? xv4.y : (j == 2) ? xv4.z : xv4.w;
        const float4* w4 = (const float4*)(rw + (size_t)(d0 + j) * NE);
        float4 w0 = w4[0], w1 = w4[1];
        part[0] += xv * w0.x; part[1] += xv * w0.y; part[2] += xv * w0.z; part[3] += xv * w0.w;
        part[4] += xv * w1.x; part[5] += xv * w1.y; part[6] += xv * w1.z; part[7] += xv * w1.w;
    }
#pragma unroll
    for (int e = 0; e < NE; e++)
#pragma unroll
        for (int o = 16; o > 0; o >>= 1) part[e] += __shfl_down_sync(0xffffffffu, part[e], o);
    __shared__ float sred[8][NE];
    const int wid = tid >> 5, lid = tid & 31;
    if (lid == 0)
#pragma unroll
        for (int e = 0; e < NE; e++) sred[wid][e] = part[e];
    __syncthreads();
    if (tid == 0) {
        float lg[NE];
#pragma unroll
        for (int e = 0; e < NE; e++) {
            float s = rb[e];
#pragma unroll
            for (int w = 0; w < 8; w++) s += sred[w][e];
            lg[e] = s;
        }
        float m = lg[0];
#pragma unroll
        for (int e = 1; e < NE; e++) m = fmaxf(m, lg[e]);
        float p[NE], s = 0.0f;
#pragma unroll
        for (int e = 0; e < NE; e++) { p[e] = expf(lg[e] - m); s += p[e]; }
        float inv = 1.0f / s;
#pragma unroll
        for (int e = 0; e < NE; e++) { p[e] *= inv; atomicAdd(&g_imp[e], p[e]); }
        int i0 = 0;
#pragma unroll
        for (int e = 1; e < NE; e++) if (p[e] > p[i0]) i0 = e;
        int i1 = (i0 == 0) ? 1 : 0;
#pragma unroll
        for (int e = 0; e < NE; e++) if (e != i0 && p[e] > p[i1]) i1 = e;
        float ps = fmaxf(p[i0] + p[i1], 1e-9f);
        int s0 = atomicAdd(&g_cnt[i0], 1);
        g_tok[i0 * CAP + s0] = t; g_wt[i0 * CAP + s0] = p[i0] / ps;
        int s1 = atomicAdd(&g_cnt[i1], 1);
        g_tok[i1 * CAP + s1] = t; g_wt[i1 * CAP + s1] = p[i1] / ps;
    }
}

__global__ void finalize_kernel(float* out, int T, long long out_size) {
    if (threadIdx.x == 0) {
        int off = 0;
        for (int e = 0; e < NE; e++) { g_off[e] = off; off += g_cnt[e]; }
        float aux = 0.0f;
        for (int e = 0; e < NE; e++)
            aux += (g_imp[e] / (float)T) * ((float)g_cnt[e] / (float)(T * 2));
        aux *= (float)NE;
        long long oi = (long long)T * D_MODEL;
        if (oi < out_size) out[oi] = aux;
    }
}

// ======================= 3xFP16 mma grouped GEMMs ==========================
// CTA tile 128(M) x 128(N), K-chunk 16, double-buffered cp.async.
// A and B both hi/lo fp16 planes [128 rows][16 k], 32B/row, 16B blocks
// XOR-swizzled (phys = c ^ ((row>>2)&1)); ALL fragments via ldmatrix.x4.
#define PL (128 * 16)

struct __align__(16) SmemMMA {
    __half Ah[2][PL], Al[2][PL];   // 16 KB
    __half Bh[2][PL], Bl[2][PL];   // 16 KB
    int   stok[128];
    float swt[128];
};

__device__ __forceinline__ void load_chunk(SmemMMA& sm, int buf, int k0,
                                           const __half* __restrict__ Ahg,
                                           const __half* __restrict__ Alg,
                                           int LDKA, const int* __restrict__ srow,
                                           const __half* __restrict__ Bhg,
                                           const __half* __restrict__ Blg,
                                           int LDKB, int n0, int tid) {
    uint32_t ahB = smem_u32(sm.Ah[buf]), alB = smem_u32(sm.Al[buf]);
    uint32_t bhB = smem_u32(sm.Bh[buf]), blB = smem_u32(sm.Bl[buf]);
#pragma unroll
    for (int it = 0; it < 2; it++) {
        int i = tid + it * 256;
        int row = i >> 2, sub = i & 3;
        int pl = sub >> 1, c = sub & 1;
        int phys = c ^ ((row >> 2) & 1);
        uint32_t dst = (pl ? alB : ahB) + row * 32 + phys * 16;
        const __half* src = (pl ? Alg : Ahg) + (size_t)srow[row] * LDKA + k0 + c * 8;
        cp16(dst, src);
    }
#pragma unroll
    for (int it = 0; it < 2; it++) {
        int i = tid + it * 256;
        int row = i >> 2, sub = i & 3;
        int pl = sub >> 1, c = sub & 1;
        int phys = c ^ ((row >> 2) & 1);
        uint32_t dst = (pl ? blB : bhB) + row * 32 + phys * 16;
        const __half* src = (pl ? Blg : Bhg) + (size_t)(n0 + row) * LDKB + k0 + c * 8;
        cp16(dst, src);
    }
}

// per-lane ldmatrix base offsets (swizzle bit invariant under +16 rows / +512B)
// B (n-tiles): matrix j -> (nt = j/2, khalf = j%2)
__device__ __forceinline__ uint32_t ldmB_off0(int warp_n, int lid) {
    int u = lid >> 3, r = lid & 7;
    int kh = u & 1;
    int nrow = warp_n + (u >> 1) * 8 + r;
    int phys = kh ^ ((nrow >> 2) & 1);
    return (uint32_t)(nrow * 32 + phys * 16);
}
// A (m-tile): matrix j: j0=r0-7/k0-7, j1=r8-15/k0-7, j2=r0-7/k8-15, j3=r8-15/k8-15
__device__ __forceinline__ uint32_t ldmA_off0(int warp_m, int lid) {
    int u = lid >> 3, r = lid & 7;
    int mrow = warp_m + (u & 1) * 8 + r;
    int kh = u >> 1;
    int phys = kh ^ ((mrow >> 2) & 1);
    return (uint32_t)(mrow * 32 + phys * 16);
}

// one K-chunk: 12 ldmatrix + 48 compensated MMAs (zero in-loop ALU)
__device__ __forceinline__ void compute_chunk(const SmemMMA& sm, int buf,
                                              uint32_t aOff0, uint32_t bOff0,
                                              float acc[2][8][4]) {
    uint32_t ahB = smem_u32(sm.Ah[buf]) + aOff0;
    uint32_t alB = smem_u32(sm.Al[buf]) + aOff0;
    uint32_t bhB = smem_u32(sm.Bh[buf]) + bOff0;
    uint32_t blB = smem_u32(sm.Bl[buf]) + bOff0;

    uint32_t ah[2][4], al[2][4];
#pragma unroll
    for (int mt = 0; mt < 2; mt++) {
        ldmx4(ah[mt][0], ah[mt][1], ah[mt][2], ah[mt][3], ahB + mt * 512);
        ldmx4(al[mt][0], al[mt][1], al[mt][2], al[mt][3], alB + mt * 512);
    }
    uint32_t bh[8][2], bl[8][2];
#pragma unroll
    for (int q = 0; q < 4; q++) {
        ldmx4(bh[2 * q][0], bh[2 * q][1], bh[2 * q + 1][0], bh[2 * q + 1][1],
              bhB + q * 512);
        ldmx4(bl[2 * q][0], bl[2 * q][1], bl[2 * q + 1][0], bl[2 * q + 1][1],
              blB + q * 512);
    }
#pragma unroll
    for (int mt = 0; mt < 2; mt++)
#pragma unroll
        for (int nt = 0; nt < 8; nt++) {
            mma_f16(acc[mt][nt], ah[mt][0], ah[mt][1], ah[mt][2], ah[mt][3],
                    bl[nt][0], bl[nt][1]);
            mma_f16(acc[mt][nt], al[mt][0], al[mt][1], al[mt][2], al[mt][3],
                    bh[nt][0], bh[nt][1]);
            mma_f16(acc[mt][nt], ah[mt][0], ah[mt][1], ah[mt][2], ah[mt][3],
                    bh[nt][0], bh[nt][1]);
        }
}

// GEMM1: Hhi/Hlo[off+m, n] = split(gelu(x[tok_m] . W1[e][:, n] + b1[e][n]))
__global__ void __launch_bounds__(256, 2) gemm1_mma(const float* __restrict__ b1) {
    __shared__ SmemMMA sm;
    const int e = blockIdx.z;
    const int cnt = g_cnt[e];
    const int m0 = blockIdx.y * 128;
    if (m0 >= cnt) return;
    const int n0 = blockIdx.x * 128;
    const int tid = threadIdx.x;
    const int wid = tid >> 5, lid = tid & 31;
    const int g = lid >> 2, tig = lid & 3;
    const int warp_m = (wid & 3) * 32, warp_n = (wid >> 2) * 64;
    const uint32_t aOff0 = ldmA_off0(warp_m, lid);
    const uint32_t bOff0 = ldmB_off0(warp_n, lid);

    if (tid < 128) sm.stok[tid] = g_tok[e * CAP + min(m0 + tid, cnt - 1)];
    __syncthreads();

    const __half* Wh = g_W1hi + (size_t)e * D_FF * D_MODEL;
    const __half* Wl = g_W1lo + (size_t)e * D_FF * D_MODEL;
    float acc[2][8][4];
#pragma unroll
    for (int a = 0; a < 2; a++)
#pragma unroll
        for (int b = 0; b < 8; b++)
#pragma unroll
            for (int c = 0; c < 4; c++) acc[a][b][c] = 0.0f;

    const int NC = D_MODEL / 16;  // 64
    load_chunk(sm, 0, 0, g_xhi, g_xlo, D_MODEL, sm.stok, Wh, Wl, D_MODEL, n0, tid);
    CP_COMMIT();
    for (int c = 0; c < NC; c++) {
        if (c + 1 < NC) {
            load_chunk(sm, (c + 1) & 1, (c + 1) * 16, g_xhi, g_xlo, D_MODEL, sm.stok,
                       Wh, Wl, D_MODEL, n0, tid);
            CP_COMMIT();
            CP_WAIT(1);
        } else {
            CP_WAIT(0);
        }
        __syncthreads();
        compute_chunk(sm, c & 1, aOff0, bOff0, acc);
        __syncthreads();
    }

    const int base = g_off[e];
#pragma unroll
    for (int mt = 0; mt < 2; mt++) {
#pragma unroll
        for (int half = 0; half < 2; half++) {
            int m = m0 + warp_m + mt * 16 + g + half * 8;
            if (m < cnt) {
                size_t rbase = (size_t)(base + m) * D_FF;
#pragma unroll
                for (int nt = 0; nt < 8; nt++) {
                    int col = n0 + warp_n + nt * 8 + 2 * tig;
                    float v0 = acc[mt][nt][half * 2 + 0] + b1[e * D_FF + col];
                    float v1 = acc[mt][nt][half * 2 + 1] + b1[e * D_FF + col + 1];
                    float o0 = 0.5f * v0 * (1.0f + erff(v0 * 0.70710678118654752f));
                    float o1 = 0.5f * v1 * (1.0f + erff(v1 * 0.70710678118654752f));
                    __half h0, l0, h1, l1;
                    hsplit(o0, h0, l0);
                    hsplit(o1, h1, l1);
                    *(__half2*)(g_Hhi + rbase + col) = __halves2half2(h0, h1);
                    *(__half2*)(g_Hlo + rbase + col) = __halves2half2(l0, l1);
                }
            }
        }
    }
}

// GEMM2: out[tok_m, n] += w_m * (H[base+m, :] . W2[e][:, n] + b2[e][n])
__global__ void __launch_bounds__(256, 2) gemm2_mma(const float* __restrict__ b2,
                                                    float* __restrict__ out) {
    __shared__ SmemMMA sm;
    __shared__ int srow[128];
    const int e = blockIdx.z;
    const int cnt = g_cnt[e];
    const int m0 = blockIdx.y * 128;
    if (m0 >= cnt) return;
    const int n0 = blockIdx.x * 128;
    const int tid = threadIdx.x;
    const int wid = tid >> 5, lid = tid & 31;
    const int g = lid >> 2, tig = lid & 3;
    const int warp_m = (wid & 3) * 32, warp_n = (wid >> 2) * 64;
    const uint32_t aOff0 = ldmA_off0(warp_m, lid);
    const uint32_t bOff0 = ldmB_off0(warp_n, lid);
    const int base = g_off[e];

    if (tid < 128) {
        int m = min(m0 + tid, cnt - 1);
        sm.stok[tid] = g_tok[e * CAP + m];
        sm.swt[tid]  = g_wt[e * CAP + m];
        srow[tid]    = base + m;
    }
    __syncthreads();

    const __half* Wh = g_W2hi + (size_t)e * D_MODEL * D_FF;
    const __half* Wl = g_W2lo + (size_t)e * D_MODEL * D_FF;
    float acc[2][8][4];
#pragma unroll
    for (int a = 0; a < 2; a++)
#pragma unroll
        for (int b = 0; b < 8; b++)
#pragma unroll
            for (int c = 0; c < 4; c++) acc[a][b][c] = 0.0f;

    const int NC = D_FF / 16;  // 128
    load_chunk(sm, 0, 0, g_Hhi, g_Hlo, D_FF, srow, Wh, Wl, D_FF, n0, tid);
    CP_COMMIT();
    for (int c = 0; c < NC; c++) {
        if (c + 1 < NC) {
            load_chunk(sm, (c + 1) & 1, (c + 1) * 16, g_Hhi, g_Hlo, D_FF, srow,
                       Wh, Wl, D_FF, n0, tid);
            CP_COMMIT();
            CP_WAIT(1);
        } else {
            CP_WAIT(0);
        }
        __syncthreads();
        compute_chunk(sm, c & 1, aOff0, bOff0, acc);
        __syncthreads();
    }

#pragma unroll
    for (int mt = 0; mt < 2; mt++) {
#pragma unroll
        for (int half = 0; half < 2; half++) {
            int ml = warp_m + mt * 16 + g + half * 8;
            int m = m0 + ml;
            if (m < cnt) {
                int tok = sm.stok[ml];
                float w = sm.swt[ml];
                float* orow = out + (size_t)tok * D_MODEL;
#pragma unroll
                for (int nt = 0; nt < 8; nt++) {
                    int col = n0 + warp_n + nt * 8 + 2 * tig;
                    float y0 = acc[mt][nt][half * 2 + 0] + b2[e * D_MODEL + col];
                    float y1 = acc[mt][nt][half * 2 + 1] + b2[e * D_MODEL + col + 1];
                    atomicAdd(&orow[col], w * y0);
                    atomicAdd(&orow[col + 1], w * y1);
                }
            }
        }
    }
}

// ===========================================================================
extern "C" void kernel_launch(void* const* d_in, const int* in_sizes, int n_in,
                              void* d_out, int out_size) {
    const float* x  = (const float*)d_in[0];
    const float* rw = (const float*)d_in[1];
    const float* rb = (const float*)d_in[2];
    const float* W1 = (const float*)d_in[3];
    const float* b1 = (const float*)d_in[4];
    const float* W2 = (const float*)d_in[5];
    const float* b2 = (const float*)d_in[6];
    float* out = (float*)d_out;

    const int T = in_sizes[0] / D_MODEL;

    zero_kernel<<<(out_size + 255) / 256, 256>>>(out, out_size);
    split_x_kernel<<<(T * D_MODEL + 255) / 256, 256>>>(x, T * D_MODEL);
    {
        dim3 blk(32, 8);
        dim3 gw1(D_FF / 32, D_MODEL / 32, NE);
        split_w1_kernel<<<gw1, blk>>>(W1);
        dim3 gw2(D_MODEL / 32, D_FF / 32, NE);
        split_w2_kernel<<<gw2, blk>>>(W2);
    }
    router_kernel<<<T, 256>>>(x, rw, rb);
    finalize_kernel<<<1, 1>>>(out, T, (long long)out_size);

    dim3 g1(D_FF / 128, (T + 127) / 128, NE);
    gemm1_mma<<<g1, 256>>>(b1);

    dim3 g2(D_MODEL / 128, (T + 127) / 128, NE);
    gemm2_mma<<<g2, 256>>>(b2, out);
}

// round 14
// speedup vs baseline: 1.0219x; 1.0219x over previous
#include <cuda_runtime.h>
#include <cuda_fp16.h>
#include <cstdint>
#include <math.h>

#define D_MODEL 1024
#define D_FF    2048
#define NE      8
#define CAP     4096
#define MAXT    4096

// ---- device scratch ----
__device__ float g_H[2 * MAXT * D_FF];   // 64 MB
__device__ __align__(16) __half g_W1hi[NE * D_FF * D_MODEL];   // [e][n][k]
__device__ __align__(16) __half g_W1lo[NE * D_FF * D_MODEL];
__device__ __align__(16) __half g_W2hi[NE * D_MODEL * D_FF];   // [e][n][k]
__device__ __align__(16) __half g_W2lo[NE * D_MODEL * D_FF];
__device__ int   g_tok[NE * CAP];
__device__ float g_wt[NE * CAP];
__device__ int   g_cnt[NE];
__device__ int   g_off[NE];
__device__ float g_imp[NE];

// ======================= portable PTX helpers ==============================
__device__ __forceinline__ uint32_t smem_u32(const void* p) {
    uint32_t a;
    asm("{ .reg .u64 t; cvta.to.shared.u64 t, %1; cvt.u32.u64 %0, t; }" : "=r"(a) : "l"(p));
    return a;
}
__device__ __forceinline__ void cp16(uint32_t smem, const void* g) {
    asm volatile("cp.async.cg.shared.global [%0], [%1], 16;" :: "r"(smem), "l"(g));
}
#define CP_COMMIT() asm volatile("cp.async.commit_group;" ::: "memory")
#define CP_WAIT(n)  asm volatile("cp.async.wait_group %0;" :: "n"(n) : "memory")

__device__ __forceinline__ void mma_f16(float* c,
                                        uint32_t a0, uint32_t a1, uint32_t a2, uint32_t a3,
                                        uint32_t b0, uint32_t b1) {
    asm volatile(
        "mma.sync.aligned.m16n8k16.row.col.f32.f16.f16.f32 "
        "{%0,%1,%2,%3}, {%4,%5,%6,%7}, {%8,%9}, {%0,%1,%2,%3};"
        : "+f"(c[0]), "+f"(c[1]), "+f"(c[2]), "+f"(c[3])
        : "r"(a0), "r"(a1), "r"(a2), "r"(a3), "r"(b0), "r"(b1));
}
__device__ __forceinline__ void ldmx4(uint32_t& r0, uint32_t& r1, uint32_t& r2, uint32_t& r3,
                                      uint32_t addr) {
    asm volatile("ldmatrix.sync.aligned.m8n8.x4.shared.b16 {%0,%1,%2,%3}, [%4];"
                 : "=r"(r0), "=r"(r1), "=r"(r2), "=r"(r3) : "r"(addr));
}

// fp16 2-way split of a float pair, packed into hi/lo __half2 bit-patterns
__device__ __forceinline__ void split2(float v0, float v1, uint32_t& hi, uint32_t& lo) {
    __half2 h2 = __floats2half2_rn(v0, v1);
    float2 hf = __half22float2(h2);
    __half2 l2 = __floats2half2_rn(v0 - hf.x, v1 - hf.y);
    hi = *reinterpret_cast<uint32_t*>(&h2);
    lo = *reinterpret_cast<uint32_t*>(&l2);
}
__device__ __forceinline__ void hsplit(float v, __half& h, __half& l) {
    h = __float2half(v);
    l = __float2half(v - __half2float(h));
}

// ======================= prep: W[e][K][N] fp32 -> hi/lo [e][N][K] fp16 =====
// Output symbols referenced from DEVICE code only (host-side symbol decay of
// __device__ arrays silently writes garbage — R5/R6/R8 bug).
template<int K, int N>
__device__ __forceinline__ void split_w_body(const float* __restrict__ W,
                                             __half* __restrict__ Whi,
                                             __half* __restrict__ Wlo) {
    __shared__ float tile[32][33];
    const int e = blockIdx.z;
    const int k0 = blockIdx.y * 32, n0 = blockIdx.x * 32;
    const int tx = threadIdx.x, ty = threadIdx.y;   // 32 x 8
    const float* Wb = W + (size_t)e * K * N;
#pragma unroll
    for (int r = 0; r < 4; r++)
        tile[ty + r * 8][tx] = Wb[(size_t)(k0 + ty + r * 8) * N + n0 + tx];
    __syncthreads();
    __half* oh = Whi + (size_t)e * K * N;
    __half* ol = Wlo + (size_t)e * K * N;
#pragma unroll
    for (int r = 0; r < 4; r++) {
        int n = n0 + ty + r * 8;
        float v = tile[tx][ty + r * 8];
        __half h, l;
        hsplit(v, h, l);
        oh[(size_t)n * K + k0 + tx] = h;
        ol[(size_t)n * K + k0 + tx] = l;
    }
}
__global__ void split_w1_kernel(const float* __restrict__ W) {
    split_w_body<D_MODEL, D_FF>(W, g_W1hi, g_W1lo);
}
__global__ void split_w2_kernel(const float* __restrict__ W) {
    split_w_body<D_FF, D_MODEL>(W, g_W2hi, g_W2lo);
}

// ======================= small kernels =====================================
__global__ void zero_kernel(float* out, int n) {
    int i = blockIdx.x * blockDim.x + threadIdx.x;
    if (i < n) out[i] = 0.0f;
    if (blockIdx.x == 0 && threadIdx.x < NE) { g_cnt[threadIdx.x] = 0; g_imp[threadIdx.x] = 0.0f; }
}

// block-per-token router; ONE float4 x-load per thread (sole change vs R12)
__global__ void router_kernel(const float* __restrict__ x,
                              const float* __restrict__ rw,
                              const float* __restrict__ rb) {
    const int t = blockIdx.x, tid = threadIdx.x;
    float part[NE];
#pragma unroll
    for (int e = 0; e < NE; e++) part[e] = 0.0f;
    float4 xv4 = ((const float4*)(x + (size_t)t * D_MODEL))[tid];
    const int d0 = tid * 4;
#pragma unroll
    for (int j = 0; j < 4; j++) {
        float xv = (j == 0) ? xv4.x : (j == 1) ? xv4.y : (j == 2) ? xv4.z : xv4.w;
        const float4* w4 = (const float4*)(rw + (size_t)(d0 + j) * NE);
        float4 w0 = w4[0], w1 = w4[1];
        part[0] += xv * w0.x; part[1] += xv * w0.y; part[2] += xv * w0.z; part[3] += xv * w0.w;
        part[4] += xv * w1.x; part[5] += xv * w1.y; part[6] += xv * w1.z; part[7] += xv * w1.w;
    }
#pragma unroll
    for (int e = 0; e < NE; e++)
#pragma unroll
        for (int o = 16; o > 0; o >>= 1) part[e] += __shfl_down_sync(0xffffffffu, part[e], o);
    __shared__ float sred[8][NE];
    const int wid = tid >> 5, lid = tid & 31;
    if (lid == 0)
#pragma unroll
        for (int e = 0; e < NE; e++) sred[wid][e] = part[e];
    __syncthreads();
    if (tid == 0) {
        float lg[NE];
#pragma unroll
        for (int e = 0; e < NE; e++) {
            float s = rb[e];
#pragma unroll
            for (int w = 0; w < 8; w++) s += sred[w][e];
            lg[e] = s;
        }
        float m = lg[0];
#pragma unroll
        for (int e = 1; e < NE; e++) m = fmaxf(m, lg[e]);
        float p[NE], s = 0.0f;
#pragma unroll
        for (int e = 0; e < NE; e++) { p[e] = expf(lg[e] - m); s += p[e]; }
        float inv = 1.0f / s;
#pragma unroll
        for (int e = 0; e < NE; e++) { p[e] *= inv; atomicAdd(&g_imp[e], p[e]); }
        int i0 = 0;
#pragma unroll
        for (int e = 1; e < NE; e++) if (p[e] > p[i0]) i0 = e;
        int i1 = (i0 == 0) ? 1 : 0;
#pragma unroll
        for (int e = 0; e < NE; e++) if (e != i0 && p[e] > p[i1]) i1 = e;
        float ps = fmaxf(p[i0] + p[i1], 1e-9f);
        int s0 = atomicAdd(&g_cnt[i0], 1);
        g_tok[i0 * CAP + s0] = t; g_wt[i0 * CAP + s0] = p[i0] / ps;
        int s1 = atomicAdd(&g_cnt[i1], 1);
        g_tok[i1 * CAP + s1] = t; g_wt[i1 * CAP + s1] = p[i1] / ps;
    }
}

__global__ void finalize_kernel(float* out, int T, long long out_size) {
    if (threadIdx.x == 0) {
        int off = 0;
        for (int e = 0; e < NE; e++) { g_off[e] = off; off += g_cnt[e]; }
        float aux = 0.0f;
        for (int e = 0; e < NE; e++)
            aux += (g_imp[e] / (float)T) * ((float)g_cnt[e] / (float)(T * 2));
        aux *= (float)NE;
        long long oi = (long long)T * D_MODEL;
        if (oi < out_size) out[oi] = aux;
    }
}

// ======================= 3xFP16 mma grouped GEMMs ==========================
// CTA tile 128(M) x 128(N), K-chunk 16, double-buffered cp.async.
// A smem: [128 rows][AST=24] fp32 (float2 fragment loads conflict-free)
// B smem: hi/lo fp16 planes [128 n][16 k], 32B/row, 16B blocks XOR-swizzled:
//   phys_block = c ^ ((n>>2)&1); B fragments loaded via ldmatrix.x4.
#define AST 24
#define BPL (128 * 16)

struct __align__(16) SmemMMA {
    float  A[2][128 * AST];        // 24576 B
    __half Bh[2][BPL], Bl[2][BPL]; // 16384 B
    int   stok[128];
    float swt[128];
};

template<int LDK>
__device__ __forceinline__ void load_chunk(SmemMMA& sm, int buf, int k0,
                                           const float* __restrict__ src_rows_base,
                                           const int* __restrict__ srow,
                                           const __half* __restrict__ Wh,
                                           const __half* __restrict__ Wl,
                                           int LDKB, int n0, int tid) {
    uint32_t aBase = smem_u32(sm.A[buf]);
    uint32_t bhB = smem_u32(sm.Bh[buf]);
    uint32_t blB = smem_u32(sm.Bl[buf]);
    // A: 128 rows x 4 float4 (fp32)
#pragma unroll
    for (int it = 0; it < 2; it++) {
        int i = tid + it * 256;
        int row = i >> 2, c = i & 3;
        const float* g = src_rows_base + (size_t)srow[row] * LDK + k0 + c * 4;
        cp16(aBase + (row * AST + c * 4) * 4, g);
    }
    // B: 128 n-rows x {hi,lo} x 2 k-halves (fp16), XOR-swizzled 16B blocks
#pragma unroll
    for (int it = 0; it < 2; it++) {
        int i = tid + it * 256;
        int row = i >> 2, sub = i & 3;
        int pl = sub >> 1, c = sub & 1;
        int phys = c ^ ((row >> 2) & 1);
        uint32_t dst = (pl ? blB : bhB) + row * 32 + phys * 16;
        const __half* src = (pl ? Wl : Wh) + (size_t)(n0 + row) * LDKB + k0 + c * 8;
        cp16(dst, src);
    }
}

// one K-chunk (full k16), 3xFP16 compensated: 48 MMAs.
// A split in-register; B fragments via 8x ldmatrix.x4 (bOff0 = per-lane offset).
__device__ __forceinline__ void compute_chunk(const SmemMMA& sm, int buf,
                                              int warp_m, int g, int tig,
                                              uint32_t bOff0,
                                              float acc[2][8][4]) {
    const float* Ab = sm.A[buf];
    uint32_t bhB = smem_u32(sm.Bh[buf]) + bOff0;
    uint32_t blB = smem_u32(sm.Bl[buf]) + bOff0;

    uint32_t ah[2][4], al[2][4];
#pragma unroll
    for (int mt = 0; mt < 2; mt++) {
        const float* p = Ab + (warp_m + mt * 16 + g) * AST;
        float2 v0 = *(const float2*)(p + 2 * tig);
        float2 v1 = *(const float2*)(p + 8 * AST + 2 * tig);
        float2 v2 = *(const float2*)(p + 2 * tig + 8);
        float2 v3 = *(const float2*)(p + 8 * AST + 2 * tig + 8);
        split2(v0.x, v0.y, ah[mt][0], al[mt][0]);
        split2(v1.x, v1.y, ah[mt][1], al[mt][1]);
        split2(v2.x, v2.y, ah[mt][2], al[mt][2]);
        split2(v3.x, v3.y, ah[mt][3], al[mt][3]);
    }
    uint32_t bh[8][2], bl[8][2];
#pragma unroll
    for (int q = 0; q < 4; q++) {
        ldmx4(bh[2 * q][0], bh[2 * q][1], bh[2 * q + 1][0], bh[2 * q + 1][1],
              bhB + q * 512);
        ldmx4(bl[2 * q][0], bl[2 * q][1], bl[2 * q + 1][0], bl[2 * q + 1][1],
              blB + q * 512);
    }
#pragma unroll
    for (int mt = 0; mt < 2; mt++)
#pragma unroll
        for (int nt = 0; nt < 8; nt++) {
            mma_f16(acc[mt][nt], ah[mt][0], ah[mt][1], ah[mt][2], ah[mt][3],
                    bl[nt][0], bl[nt][1]);
            mma_f16(acc[mt][nt], al[mt][0], al[mt][1], al[mt][2], al[mt][3],
                    bh[nt][0], bh[nt][1]);
            mma_f16(acc[mt][nt], ah[mt][0], ah[mt][1], ah[mt][2], ah[mt][3],
                    bh[nt][0], bh[nt][1]);
        }
}

// per-lane ldmatrix base offset for q=0: matrices j=0..3 -> (nt = j/2, khalf = j%2);
// lane l = 8j + r supplies row r of matrix j.
__device__ __forceinline__ uint32_t ldm_off0(int warp_n, int lid) {
    int u = lid >> 3, r = lid & 7;
    int kh = u & 1;
    int nrow = warp_n + (u >> 1) * 8 + r;
    int phys = kh ^ ((nrow >> 2) & 1);
    return (uint32_t)(nrow * 32 + phys * 16);
}

// GEMM1: H[off+m, n] = gelu(x[tok_m] . W1[e][:, n] + b1[e][n])
__global__ void __launch_bounds__(256, 2) gemm1_mma(const float* __restrict__ x,
                                                    const float* __restrict__ b1) {
    __shared__ SmemMMA sm;
    const int e = blockIdx.z;
    const int cnt = g_cnt[e];
    const int m0 = blockIdx.y * 128;
    if (m0 >= cnt) return;
    const int n0 = blockIdx.x * 128;
    const int tid = threadIdx.x;
    const int wid = tid >> 5, lid = tid & 31;
    const int g = lid >> 2, tig = lid & 3;
    const int warp_m = (wid & 3) * 32, warp_n = (wid >> 2) * 64;
    const uint32_t bOff0 = ldm_off0(warp_n, lid);

    if (tid < 128) sm.stok[tid] = g_tok[e * CAP + min(m0 + tid, cnt - 1)];
    __syncthreads();

    const __half* Wh = g_W1hi + (size_t)e * D_FF * D_MODEL;
    const __half* Wl = g_W1lo + (size_t)e * D_FF * D_MODEL;
    float acc[2][8][4];
#pragma unroll
    for (int a = 0; a < 2; a++)
#pragma unroll
        for (int b = 0; b < 8; b++)
#pragma unroll
            for (int c = 0; c < 4; c++) acc[a][b][c] = 0.0f;

    const int NC = D_MODEL / 16;  // 64
    load_chunk<D_MODEL>(sm, 0, 0, x, sm.stok, Wh, Wl, D_MODEL, n0, tid);
    CP_COMMIT();
    for (int c = 0; c < NC; c++) {
        if (c + 1 < NC) {
            load_chunk<D_MODEL>(sm, (c + 1) & 1, (c + 1) * 16, x, sm.stok, Wh, Wl, D_MODEL, n0, tid);
            CP_COMMIT();
            CP_WAIT(1);
        } else {
            CP_WAIT(0);
        }
        __syncthreads();
        compute_chunk(sm, c & 1, warp_m, g, tig, bOff0, acc);
        __syncthreads();
    }

    const int base = g_off[e];
#pragma unroll
    for (int mt = 0; mt < 2; mt++) {
#pragma unroll
        for (int half = 0; half < 2; half++) {
            int m = m0 + warp_m + mt * 16 + g + half * 8;
            if (m < cnt) {
                float* hrow = g_H + (size_t)(base + m) * D_FF;
#pragma unroll
                for (int nt = 0; nt < 8; nt++) {
                    int col = n0 + warp_n + nt * 8 + 2 * tig;
                    float v0 = acc[mt][nt][half * 2 + 0] + b1[e * D_FF + col];
                    float v1 = acc[mt][nt][half * 2 + 1] + b1[e * D_FF + col + 1];
                    float2 o;
                    o.x = 0.5f * v0 * (1.0f + erff(v0 * 0.70710678118654752f));
                    o.y = 0.5f * v1 * (1.0f + erff(v1 * 0.70710678118654752f));
                    *(float2*)(hrow + col) = o;
                }
            }
        }
    }
}

// GEMM2: out[tok_m, n] += w_m * (H[base+m, :] . W2[e][:, n] + b2[e][n])
__global__ void __launch_bounds__(256, 2) gemm2_mma(const float* __restrict__ b2,
                                                    float* __restrict__ out) {
    __shared__ SmemMMA sm;
    __shared__ int srow[128];
    const int e = blockIdx.z;
    const int cnt = g_cnt[e];
    const int m0 = blockIdx.y * 128;
    if (m0 >= cnt) return;
    const int n0 = blockIdx.x * 128;
    const int tid = threadIdx.x;
    const int wid = tid >> 5, lid = tid & 31;
    const int g = lid >> 2, tig = lid & 3;
    const int warp_m = (wid & 3) * 32, warp_n = (wid >> 2) * 64;
    const uint32_t bOff0 = ldm_off0(warp_n, lid);
    const int base = g_off[e];

    if (tid < 128) {
        int m = min(m0 + tid, cnt - 1);
        sm.stok[tid] = g_tok[e * CAP + m];
        sm.swt[tid]  = g_wt[e * CAP + m];
        srow[tid]    = base + m;
    }
    __syncthreads();

    const __half* Wh = g_W2hi + (size_t)e * D_MODEL * D_FF;
    const __half* Wl = g_W2lo + (size_t)e * D_MODEL * D_FF;
    float acc[2][8][4];
#pragma unroll
    for (int a = 0; a < 2; a++)
#pragma unroll
        for (int b = 0; b < 8; b++)
#pragma unroll
            for (int c = 0; c < 4; c++) acc[a][b][c] = 0.0f;

    const int NC = D_FF / 16;  // 128
    load_chunk<D_FF>(sm, 0, 0, g_H, srow, Wh, Wl, D_FF, n0, tid);
    CP_COMMIT();
    for (int c = 0; c < NC; c++) {
        if (c + 1 < NC) {
            load_chunk<D_FF>(sm, (c + 1) & 1, (c + 1) * 16, g_H, srow, Wh, Wl, D_FF, n0, tid);
            CP_COMMIT();
            CP_WAIT(1);
        } else {
            CP_WAIT(0);
        }
        __syncthreads();
        compute_chunk(sm, c & 1, warp_m, g, tig, bOff0, acc);
        __syncthreads();
    }

#pragma unroll
    for (int mt = 0; mt < 2; mt++) {
#pragma unroll
        for (int half = 0; half < 2; half++) {
            int ml = warp_m + mt * 16 + g + half * 8;
            int m = m0 + ml;
            if (m < cnt) {
                int tok = sm.stok[ml];
                float w = sm.swt[ml];
                float* orow = out + (size_t)tok * D_MODEL;
#pragma unroll
                for (int nt = 0; nt < 8; nt++) {
                    int col = n0 + warp_n + nt * 8 + 2 * tig;
                    float y0 = acc[mt][nt][half * 2 + 0] + b2[e * D_MODEL + col];
                    float y1 = acc[mt][nt][half * 2 + 1] + b2[e * D_MODEL + col + 1];
                    atomicAdd(&orow[col], w * y0);
                    atomicAdd(&orow[col + 1], w * y1);
                }
            }
        }
    }
}

// ===========================================================================
extern "C" void kernel_launch(void* const* d_in, const int* in_sizes, int n_in,
                              void* d_out, int out_size) {
    const float* x  = (const float*)d_in[0];
    const float* rw = (const float*)d_in[1];
    const float* rb = (const float*)d_in[2];
    const float* W1 = (const float*)d_in[3];
    const float* b1 = (const float*)d_in[4];
    const float* W2 = (const float*)d_in[5];
    const float* b2 = (const float*)d_in[6];
    float* out = (float*)d_out;

    const int T = in_sizes[0] / D_MODEL;

    zero_kernel<<<(out_size + 255) / 256, 256>>>(out, out_size);
    {
        dim3 blk(32, 8);
        dim3 gw1(D_FF / 32, D_MODEL / 32, NE);
        split_w1_kernel<<<gw1, blk>>>(W1);
        dim3 gw2(D_MODEL / 32, D_FF / 32, NE);
        split_w2_kernel<<<gw2, blk>>>(W2);
    }
    router_kernel<<<T, 256>>>(x, rw, rb);
    finalize_kernel<<<1, 1>>>(out, T, (long long)out_size);

    dim3 g1(D_FF / 128, (T + 127) / 128, NE);
    gemm1_mma<<<g1, 256>>>(x, b1);

    dim3 g2(D_MODEL / 128, (T + 127) / 128, NE);
    gemm2_mma<<<g2, 256>>>(b2, out);
}

// round 15
// speedup vs baseline: 1.0809x; 1.0577x over previous
#include <cuda_runtime.h>
#include <cuda_fp16.h>
#include <cstdint>
#include <math.h>

#define D_MODEL 1024
#define D_FF    2048
#define NE      8
#define CAP     4096
#define MAXT    4096

// ---- device scratch ----
__device__ float g_H[2 * MAXT * D_FF];   // 64 MB
__device__ __align__(16) __half g_W1hi[NE * D_FF * D_MODEL];   // [e][n][k]
__device__ __align__(16) __half g_W1lo[NE * D_FF * D_MODEL];
__device__ __align__(16) __half g_W2hi[NE * D_MODEL * D_FF];   // [e][n][k]
__device__ __align__(16) __half g_W2lo[NE * D_MODEL * D_FF];
__device__ __align__(16) float g_rwT[NE * D_MODEL];            // [e][d]
__device__ int   g_tok[NE * CAP];
__device__ float g_wt[NE * CAP];
__device__ int   g_cnt[NE];
__device__ int   g_off[NE];
__device__ float g_imp[NE];

// ======================= portable PTX helpers ==============================
__device__ __forceinline__ uint32_t smem_u32(const void* p) {
    uint32_t a;
    asm("{ .reg .u64 t; cvta.to.shared.u64 t, %1; cvt.u32.u64 %0, t; }" : "=r"(a) : "l"(p));
    return a;
}
__device__ __forceinline__ void cp16(uint32_t smem, const void* g) {
    asm volatile("cp.async.cg.shared.global [%0], [%1], 16;" :: "r"(smem), "l"(g));
}
#define CP_COMMIT() asm volatile("cp.async.commit_group;" ::: "memory")
#define CP_WAIT(n)  asm volatile("cp.async.wait_group %0;" :: "n"(n) : "memory")

__device__ __forceinline__ void mma_f16(float* c,
                                        uint32_t a0, uint32_t a1, uint32_t a2, uint32_t a3,
                                        uint32_t b0, uint32_t b1) {
    asm volatile(
        "mma.sync.aligned.m16n8k16.row.col.f32.f16.f16.f32 "
        "{%0,%1,%2,%3}, {%4,%5,%6,%7}, {%8,%9}, {%0,%1,%2,%3};"
        : "+f"(c[0]), "+f"(c[1]), "+f"(c[2]), "+f"(c[3])
        : "r"(a0), "r"(a1), "r"(a2), "r"(a3), "r"(b0), "r"(b1));
}
__device__ __forceinline__ void ldmx4(uint32_t& r0, uint32_t& r1, uint32_t& r2, uint32_t& r3,
                                      uint32_t addr) {
    asm volatile("ldmatrix.sync.aligned.m8n8.x4.shared.b16 {%0,%1,%2,%3}, [%4];"
                 : "=r"(r0), "=r"(r1), "=r"(r2), "=r"(r3) : "r"(addr));
}

// fp16 2-way split of a float pair, packed into hi/lo __half2 bit-patterns
__device__ __forceinline__ void split2(float v0, float v1, uint32_t& hi, uint32_t& lo) {
    __half2 h2 = __floats2half2_rn(v0, v1);
    float2 hf = __half22float2(h2);
    __half2 l2 = __floats2half2_rn(v0 - hf.x, v1 - hf.y);
    hi = *reinterpret_cast<uint32_t*>(&h2);
    lo = *reinterpret_cast<uint32_t*>(&l2);
}
__device__ __forceinline__ void hsplit(float v, __half& h, __half& l) {
    h = __float2half(v);
    l = __float2half(v - __half2float(h));
}

// ======================= prep: W[e][K][N] fp32 -> hi/lo [e][N][K] fp16 =====
// Output symbols referenced from DEVICE code only (host-side symbol decay of
// __device__ arrays silently writes garbage — R5/R6/R8 bug).
template<int K, int N>
__device__ __forceinline__ void split_w_body(const float* __restrict__ W,
                                             __half* __restrict__ Whi,
                                             __half* __restrict__ Wlo) {
    __shared__ float tile[32][33];
    const int e = blockIdx.z;
    const int k0 = blockIdx.y * 32, n0 = blockIdx.x * 32;
    const int tx = threadIdx.x, ty = threadIdx.y;   // 32 x 8
    const float* Wb = W + (size_t)e * K * N;
#pragma unroll
    for (int r = 0; r < 4; r++)
        tile[ty + r * 8][tx] = Wb[(size_t)(k0 + ty + r * 8) * N + n0 + tx];
    __syncthreads();
    __half* oh = Whi + (size_t)e * K * N;
    __half* ol = Wlo + (size_t)e * K * N;
#pragma unroll
    for (int r = 0; r < 4; r++) {
        int n = n0 + ty + r * 8;
        float v = tile[tx][ty + r * 8];
        __half h, l;
        hsplit(v, h, l);
        oh[(size_t)n * K + k0 + tx] = h;
        ol[(size_t)n * K + k0 + tx] = l;
    }
}
__global__ void split_w1_kernel(const float* __restrict__ W) {
    split_w_body<D_MODEL, D_FF>(W, g_W1hi, g_W1lo);
}
__global__ void split_w2_kernel(const float* __restrict__ W) {
    split_w_body<D_FF, D_MODEL>(W, g_W2hi, g_W2lo);
}

// rw[d][e] -> g_rwT[e][d]  (32 KB, one block)
__global__ void transpose_rw_kernel(const float* __restrict__ rw) {
    for (int i = threadIdx.x; i < NE * D_MODEL; i += 256) {
        int e = i >> 10, d = i & (D_MODEL - 1);
        g_rwT[i] = rw[d * NE + e];
    }
}

// ======================= small kernels =====================================
__global__ void zero_kernel(float* out, int n) {
    int i = blockIdx.x * blockDim.x + threadIdx.x;
    if (i < n) out[i] = 0.0f;
    if (blockIdx.x == 0 && threadIdx.x < NE) { g_cnt[threadIdx.x] = 0; g_imp[threadIdx.x] = 0.0f; }
}

// ======================= router v3 =========================================
// 16 tokens/block (grid T/16); rwT staged in smem; warp computes 2 tokens;
// importance/count atomics aggregated per block (global same-address atomics
// drop from ~41K to ~4K spread over 16 addresses).
#define RTOK 16
__global__ void __launch_bounds__(256) router_kernel(const float* __restrict__ x,
                                                     const float* __restrict__ rb) {
    __shared__ float rwT_s[NE * D_MODEL];   // 32 KB
    __shared__ float s_imp[NE];
    __shared__ int   s_cnt[NE], s_base[NE];
    __shared__ int   s_i0[RTOK], s_i1[RTOK], s_l0[RTOK], s_l1[RTOK];
    __shared__ float s_w0[RTOK], s_w1[RTOK];
    const int tid = threadIdx.x, wid = tid >> 5, lid = tid & 31;

    for (int i = tid; i < NE * D_MODEL / 4; i += 256)
        ((float4*)rwT_s)[i] = ((const float4*)g_rwT)[i];
    if (tid < NE) { s_imp[tid] = 0.0f; s_cnt[tid] = 0; }
    __syncthreads();

#pragma unroll
    for (int q = 0; q < 2; q++) {
        const int tl = wid * 2 + q;                 // 0..15
        const int t = blockIdx.x * RTOK + tl;
        float part[NE];
#pragma unroll
        for (int e = 0; e < NE; e++) part[e] = 0.0f;
        const float4* xr = (const float4*)(x + (size_t)t * D_MODEL);
#pragma unroll
        for (int i = 0; i < 8; i++) {
            float4 xv = xr[i * 32 + lid];
            const int d = i * 128 + 4 * lid;
#pragma unroll
            for (int e = 0; e < NE; e++) {
                float4 w = *(const float4*)&rwT_s[e * D_MODEL + d];
                part[e] += xv.x * w.x + xv.y * w.y + xv.z * w.z + xv.w * w.w;
            }
        }
#pragma unroll
        for (int e = 0; e < NE; e++)
#pragma unroll
            for (int o = 16; o > 0; o >>= 1)
                part[e] += __shfl_down_sync(0xffffffffu, part[e], o);
        if (lid == 0) {
            float lg[NE];
#pragma unroll
            for (int e = 0; e < NE; e++) lg[e] = part[e] + rb[e];
            float m = lg[0];
#pragma unroll
            for (int e = 1; e < NE; e++) m = fmaxf(m, lg[e]);
            float p[NE], s = 0.0f;
#pragma unroll
            for (int e = 0; e < NE; e++) { p[e] = expf(lg[e] - m); s += p[e]; }
            float inv = 1.0f / s;
#pragma unroll
            for (int e = 0; e < NE; e++) { p[e] *= inv; atomicAdd(&s_imp[e], p[e]); }
            int i0 = 0;
#pragma unroll
            for (int e = 1; e < NE; e++) if (p[e] > p[i0]) i0 = e;
            int i1 = (i0 == 0) ? 1 : 0;
#pragma unroll
            for (int e = 0; e < NE; e++) if (e != i0 && p[e] > p[i1]) i1 = e;
            float ps = fmaxf(p[i0] + p[i1], 1e-9f);
            s_i0[tl] = i0; s_i1[tl] = i1;
            s_w0[tl] = p[i0] / ps; s_w1[tl] = p[i1] / ps;
            s_l0[tl] = atomicAdd(&s_cnt[i0], 1);
            s_l1[tl] = atomicAdd(&s_cnt[i1], 1);
        }
    }
    __syncthreads();
    if (tid < NE) {
        s_base[tid] = atomicAdd(&g_cnt[tid], s_cnt[tid]);
        atomicAdd(&g_imp[tid], s_imp[tid]);
    }
    __syncthreads();
    if (tid < RTOK) {
        int t = blockIdx.x * RTOK + tid;
        int i0 = s_i0[tid], i1 = s_i1[tid];
        int p0 = s_base[i0] + s_l0[tid];
        g_tok[i0 * CAP + p0] = t; g_wt[i0 * CAP + p0] = s_w0[tid];
        int p1 = s_base[i1] + s_l1[tid];
        g_tok[i1 * CAP + p1] = t; g_wt[i1 * CAP + p1] = s_w1[tid];
    }
}

__global__ void finalize_kernel(float* out, int T, long long out_size) {
    if (threadIdx.x == 0) {
        int off = 0;
        for (int e = 0; e < NE; e++) { g_off[e] = off; off += g_cnt[e]; }
        float aux = 0.0f;
        for (int e = 0; e < NE; e++)
            aux += (g_imp[e] / (float)T) * ((float)g_cnt[e] / (float)(T * 2));
        aux *= (float)NE;
        long long oi = (long long)T * D_MODEL;
        if (oi < out_size) out[oi] = aux;
    }
}

// ======================= 3xFP16 mma grouped GEMMs ==========================
// CTA tile 128(M) x 128(N), K-chunk 16, double-buffered cp.async.
// A smem: [128 rows][AST=24] fp32 (float2 fragment loads conflict-free)
// B smem: hi/lo fp16 planes [128 n][16 k], 32B/row, 16B blocks XOR-swizzled:
//   phys_block = c ^ ((n>>2)&1); B fragments loaded via ldmatrix.x4.
#define AST 24
#define BPL (128 * 16)

struct __align__(16) SmemMMA {
    float  A[2][128 * AST];        // 24576 B
    __half Bh[2][BPL], Bl[2][BPL]; // 16384 B
    int   stok[128];
    float swt[128];
};

template<int LDK>
__device__ __forceinline__ void load_chunk(SmemMMA& sm, int buf, int k0,
                                           const float* __restrict__ src_rows_base,
                                           const int* __restrict__ srow,
                                           const __half* __restrict__ Wh,
                                           const __half* __restrict__ Wl,
                                           int LDKB, int n0, int tid) {
    uint32_t aBase = smem_u32(sm.A[buf]);
    uint32_t bhB = smem_u32(sm.Bh[buf]);
    uint32_t blB = smem_u32(sm.Bl[buf]);
    // A: 128 rows x 4 float4 (fp32)
#pragma unroll
    for (int it = 0; it < 2; it++) {
        int i = tid + it * 256;
        int row = i >> 2, c = i & 3;
        const float* g = src_rows_base + (size_t)srow[row] * LDK + k0 + c * 4;
        cp16(aBase + (row * AST + c * 4) * 4, g);
    }
    // B: 128 n-rows x {hi,lo} x 2 k-halves (fp16), XOR-swizzled 16B blocks
#pragma unroll
    for (int it = 0; it < 2; it++) {
        int i = tid + it * 256;
        int row = i >> 2, sub = i & 3;
        int pl = sub >> 1, c = sub & 1;
        int phys = c ^ ((row >> 2) & 1);
        uint32_t dst = (pl ? blB : bhB) + row * 32 + phys * 16;
        const __half* src = (pl ? Wl : Wh) + (size_t)(n0 + row) * LDKB + k0 + c * 8;
        cp16(dst, src);
    }
}

// one K-chunk (full k16), 3xFP16 compensated: 48 MMAs.
// A split in-register; B fragments via 8x ldmatrix.x4 (bOff0 = per-lane offset).
__device__ __forceinline__ void compute_chunk(const SmemMMA& sm, int buf,
                                              int warp_m, int g, int tig,
                                              uint32_t bOff0,
                                              float acc[2][8][4]) {
    const float* Ab = sm.A[buf];
    uint32_t bhB = smem_u32(sm.Bh[buf]) + bOff0;
    uint32_t blB = smem_u32(sm.Bl[buf]) + bOff0;

    uint32_t ah[2][4], al[2][4];
#pragma unroll
    for (int mt = 0; mt < 2; mt++) {
        const float* p = Ab + (warp_m + mt * 16 + g) * AST;
        float2 v0 = *(const float2*)(p + 2 * tig);
        float2 v1 = *(const float2*)(p + 8 * AST + 2 * tig);
        float2 v2 = *(const float2*)(p + 2 * tig + 8);
        float2 v3 = *(const float2*)(p + 8 * AST + 2 * tig + 8);
        split2(v0.x, v0.y, ah[mt][0], al[mt][0]);
        split2(v1.x, v1.y, ah[mt][1], al[mt][1]);
        split2(v2.x, v2.y, ah[mt][2], al[mt][2]);
        split2(v3.x, v3.y, ah[mt][3], al[mt][3]);
    }
    uint32_t bh[8][2], bl[8][2];
#pragma unroll
    for (int q = 0; q < 4; q++) {
        ldmx4(bh[2 * q][0], bh[2 * q][1], bh[2 * q + 1][0], bh[2 * q + 1][1],
              bhB + q * 512);
        ldmx4(bl[2 * q][0], bl[2 * q][1], bl[2 * q + 1][0], bl[2 * q + 1][1],
              blB + q * 512);
    }
#pragma unroll
    for (int mt = 0; mt < 2; mt++)
#pragma unroll
        for (int nt = 0; nt < 8; nt++) {
            mma_f16(acc[mt][nt], ah[mt][0], ah[mt][1], ah[mt][2], ah[mt][3],
                    bl[nt][0], bl[nt][1]);
            mma_f16(acc[mt][nt], al[mt][0], al[mt][1], al[mt][2], al[mt][3],
                    bh[nt][0], bh[nt][1]);
            mma_f16(acc[mt][nt], ah[mt][0], ah[mt][1], ah[mt][2], ah[mt][3],
                    bh[nt][0], bh[nt][1]);
        }
}

// per-lane ldmatrix base offset for q=0: matrices j=0..3 -> (nt = j/2, khalf = j%2);
// lane l = 8j + r supplies row r of matrix j.
__device__ __forceinline__ uint32_t ldm_off0(int warp_n, int lid) {
    int u = lid >> 3, r = lid & 7;
    int kh = u & 1;
    int nrow = warp_n + (u >> 1) * 8 + r;
    int phys = kh ^ ((nrow >> 2) & 1);
    return (uint32_t)(nrow * 32 + phys * 16);
}

// GEMM1: H[off+m, n] = gelu(x[tok_m] . W1[e][:, n] + b1[e][n])
__global__ void __launch_bounds__(256, 2) gemm1_mma(const float* __restrict__ x,
                                                    const float* __restrict__ b1) {
    __shared__ SmemMMA sm;
    const int e = blockIdx.z;
    const int cnt = g_cnt[e];
    const int m0 = blockIdx.y * 128;
    if (m0 >= cnt) return;
    const int n0 = blockIdx.x * 128;
    const int tid = threadIdx.x;
    const int wid = tid >> 5, lid = tid & 31;
    const int g = lid >> 2, tig = lid & 3;
    const int warp_m = (wid & 3) * 32, warp_n = (wid >> 2) * 64;
    const uint32_t bOff0 = ldm_off0(warp_n, lid);

    if (tid < 128) sm.stok[tid] = g_tok[e * CAP + min(m0 + tid, cnt - 1)];
    __syncthreads();

    const __half* Wh = g_W1hi + (size_t)e * D_FF * D_MODEL;
    const __half* Wl = g_W1lo + (size_t)e * D_FF * D_MODEL;
    float acc[2][8][4];
#pragma unroll
    for (int a = 0; a < 2; a++)
#pragma unroll
        for (int b = 0; b < 8; b++)
#pragma unroll
            for (int c = 0; c < 4; c++) acc[a][b][c] = 0.0f;

    const int NC = D_MODEL / 16;  // 64
    load_chunk<D_MODEL>(sm, 0, 0, x, sm.stok, Wh, Wl, D_MODEL, n0, tid);
    CP_COMMIT();
    for (int c = 0; c < NC; c++) {
        if (c + 1 < NC) {
            load_chunk<D_MODEL>(sm, (c + 1) & 1, (c + 1) * 16, x, sm.stok, Wh, Wl, D_MODEL, n0, tid);
            CP_COMMIT();
            CP_WAIT(1);
        } else {
            CP_WAIT(0);
        }
        __syncthreads();
        compute_chunk(sm, c & 1, warp_m, g, tig, bOff0, acc);
        __syncthreads();
    }

    const int base = g_off[e];
#pragma unroll
    for (int mt = 0; mt < 2; mt++) {
#pragma unroll
        for (int half = 0; half < 2; half++) {
            int m = m0 + warp_m + mt * 16 + g + half * 8;
            if (m < cnt) {
                float* hrow = g_H + (size_t)(base + m) * D_FF;
#pragma unroll
                for (int nt = 0; nt < 8; nt++) {
                    int col = n0 + warp_n + nt * 8 + 2 * tig;
                    float v0 = acc[mt][nt][half * 2 + 0] + b1[e * D_FF + col];
                    float v1 = acc[mt][nt][half * 2 + 1] + b1[e * D_FF + col + 1];
                    float2 o;
                    o.x = 0.5f * v0 * (1.0f + erff(v0 * 0.70710678118654752f));
                    o.y = 0.5f * v1 * (1.0f + erff(v1 * 0.70710678118654752f));
                    *(float2*)(hrow + col) = o;
                }
            }
        }
    }
}

// GEMM2: out[tok_m, n] += w_m * (H[base+m, :] . W2[e][:, n] + b2[e][n])
__global__ void __launch_bounds__(256, 2) gemm2_mma(const float* __restrict__ b2,
                                                    float* __restrict__ out) {
    __shared__ SmemMMA sm;
    __shared__ int srow[128];
    const int e = blockIdx.z;
    const int cnt = g_cnt[e];
    const int m0 = blockIdx.y * 128;
    if (m0 >= cnt) return;
    const int n0 = blockIdx.x * 128;
    const int tid = threadIdx.x;
    const int wid = tid >> 5, lid = tid & 31;
    const int g = lid >> 2, tig = lid & 3;
    const int warp_m = (wid & 3) * 32, warp_n = (wid >> 2) * 64;
    const uint32_t bOff0 = ldm_off0(warp_n, lid);
    const int base = g_off[e];

    if (tid < 128) {
        int m = min(m0 + tid, cnt - 1);
        sm.stok[tid] = g_tok[e * CAP + m];
        sm.swt[tid]  = g_wt[e * CAP + m];
        srow[tid]    = base + m;
    }
    __syncthreads();

    const __half* Wh = g_W2hi + (size_t)e * D_MODEL * D_FF;
    const __half* Wl = g_W2lo + (size_t)e * D_MODEL * D_FF;
    float acc[2][8][4];
#pragma unroll
    for (int a = 0; a < 2; a++)
#pragma unroll
        for (int b = 0; b < 8; b++)
#pragma unroll
            for (int c = 0; c < 4; c++) acc[a][b][c] = 0.0f;

    const int NC = D_FF / 16;  // 128
    load_chunk<D_FF>(sm, 0, 0, g_H, srow, Wh, Wl, D_FF, n0, tid);
    CP_COMMIT();
    for (int c = 0; c < NC; c++) {
        if (c + 1 < NC) {
            load_chunk<D_FF>(sm, (c + 1) & 1, (c + 1) * 16, g_H, srow, Wh, Wl, D_FF, n0, tid);
            CP_COMMIT();
            CP_WAIT(1);
        } else {
            CP_WAIT(0);
        }
        __syncthreads();
        compute_chunk(sm, c & 1, warp_m, g, tig, bOff0, acc);
        __syncthreads();
    }

#pragma unroll
    for (int mt = 0; mt < 2; mt++) {
#pragma unroll
        for (int half = 0; half < 2; half++) {
            int ml = warp_m + mt * 16 + g + half * 8;
            int m = m0 + ml;
            if (m < cnt) {
                int tok = sm.stok[ml];
                float w = sm.swt[ml];
                float* orow = out + (size_t)tok * D_MODEL;
#pragma unroll
                for (int nt = 0; nt < 8; nt++) {
                    int col = n0 + warp_n + nt * 8 + 2 * tig;
                    float y0 = acc[mt][nt][half * 2 + 0] + b2[e * D_MODEL + col];
                    float y1 = acc[mt][nt][half * 2 + 1] + b2[e * D_MODEL + col + 1];
                    atomicAdd(&orow[col], w * y0);
                    atomicAdd(&orow[col + 1], w * y1);
                }
            }
        }
    }
}

// ===========================================================================
extern "C" void kernel_launch(void* const* d_in, const int* in_sizes, int n_in,
                              void* d_out, int out_size) {
    const float* x  = (const float*)d_in[0];
    const float* rw = (const float*)d_in[1];
    const float* rb = (const float*)d_in[2];
    const float* W1 = (const float*)d_in[3];
    const float* b1 = (const float*)d_in[4];
    const float* W2 = (const float*)d_in[5];
    const float* b2 = (const float*)d_in[6];
    float* out = (float*)d_out;

    const int T = in_sizes[0] / D_MODEL;

    zero_kernel<<<(out_size + 255) / 256, 256>>>(out, out_size);
    transpose_rw_kernel<<<1, 256>>>(rw);
    {
        dim3 blk(32, 8);
        dim3 gw1(D_FF / 32, D_MODEL / 32, NE);
        split_w1_kernel<<<gw1, blk>>>(W1);
        dim3 gw2(D_MODEL / 32, D_FF / 32, NE);
        split_w2_kernel<<<gw2, blk>>>(W2);
    }
    router_kernel<<<T / RTOK, 256>>>(x, rb);
    finalize_kernel<<<1, 1>>>(out, T, (long long)out_size);

    dim3 g1(D_FF / 128, (T + 127) / 128, NE);
    gemm1_mma<<<g1, 256>>>(x, b1);

    dim3 g2(D_MODEL / 128, (T + 127) / 128, NE);
    gemm2_mma<<<g2, 256>>>(b2, out);
}